// round 8
// baseline (speedup 1.0000x reference)
#include <cuda_runtime.h>
#include <cstdint>

#define CHAR_VOCAB 1001
#define EMB 256
#define H 192
#define G3 576   // 3*H
#define BATCH 32
#define SEQL 2048
#define NSPAN 512

// cluster split
#define JH 96            // outputs per CTA
#define KS 4             // K-split ways
#define KC 48            // K per slice
#define NTHR (JH * KS)   // 384 threads

typedef unsigned long long u64;

// ---------------- scratch (no cudaMalloc allowed) ----------------
__device__ float g_proj[2][CHAR_VOCAB * G3];                 // 2 x 2.3 MB
__device__ float g_allh[(size_t)BATCH * SEQL * 2 * H];       // 100.7 MB

// ---------------- kernel 1: proj tables (unchanged, verified) ----------------
#define VB 16
__global__ void proj_kernel(const float* __restrict__ emb,
                            const float* __restrict__ w_ih_f, const float* __restrict__ b_ih_f,
                            const float* __restrict__ w_ih_b, const float* __restrict__ b_ih_b) {
    __shared__ float embs[VB][EMB];
    const int dir = blockIdx.y;
    const float* __restrict__ w  = dir ? w_ih_b : w_ih_f;
    const float* __restrict__ bi = dir ? b_ih_b : b_ih_f;
    const int v0 = blockIdx.x * VB;

    for (int i = threadIdx.x; i < VB * EMB; i += blockDim.x) {
        int v = v0 + i / EMB;
        embs[i / EMB][i % EMB] = (v < CHAR_VOCAB) ? emb[(size_t)v * EMB + (i % EMB)] : 0.f;
    }
    __syncthreads();

    const int g = threadIdx.x;  // 0..575
    float acc[VB];
#pragma unroll
    for (int i = 0; i < VB; i++) acc[i] = 0.f;

    const float4* __restrict__ w4 = (const float4*)(w + (size_t)g * EMB);
    for (int e4 = 0; e4 < EMB / 4; e4++) {
        float4 wv = w4[e4];
#pragma unroll
        for (int i = 0; i < VB; i++) {
            float4 ev = *(const float4*)&embs[i][e4 * 4];
            acc[i] = fmaf(wv.x, ev.x, fmaf(wv.y, ev.y, fmaf(wv.z, ev.z, fmaf(wv.w, ev.w, acc[i]))));
        }
    }
    float bb = bi[g];
#pragma unroll
    for (int i = 0; i < VB; i++) {
        int v = v0 + i;
        if (v < CHAR_VOCAB) g_proj[dir][(size_t)v * G3 + g] = acc[i] + bb;
    }
}

// ---------------- PTX helpers ----------------
__device__ __forceinline__ uint32_t smem_u32(const void* p) {
    uint32_t a;
    asm("{ .reg .u64 t; cvta.to.shared.u64 t, %1; cvt.u32.u64 %0, t; }" : "=r"(a) : "l"(p));
    return a;
}
__device__ __forceinline__ uint32_t mapa_u32(uint32_t laddr, uint32_t peer) {
    uint32_t r;
    asm("mapa.shared::cluster.u32 %0, %1, %2;" : "=r"(r) : "r"(laddr), "r"(peer));
    return r;
}
__device__ __forceinline__ void mbar_init(uint32_t a, uint32_t cnt) {
    asm volatile("mbarrier.init.shared.b64 [%0], %1;" :: "r"(a), "r"(cnt) : "memory");
}
__device__ __forceinline__ void mbar_arrive_local(uint32_t a) {
    asm volatile("mbarrier.arrive.release.cluster.shared::cta.b64 _, [%0];" :: "r"(a) : "memory");
}
__device__ __forceinline__ void mbar_arrive_remote(uint32_t ra) {
    asm volatile("mbarrier.arrive.release.cluster.shared::cluster.b64 _, [%0];" :: "r"(ra) : "memory");
}
__device__ __forceinline__ void st_remote_f32(uint32_t raddr, float v) {
    asm volatile("st.shared::cluster.b32 [%0], %1;" :: "r"(raddr), "r"(__float_as_uint(v)) : "memory");
}
__device__ __forceinline__ void mbar_wait_parity(uint32_t a, uint32_t parity) {
    uint32_t done;
    asm volatile("{\n\t.reg .pred p;\n\t"
        "mbarrier.try_wait.parity.acquire.cluster.shared::cta.b64 p, [%1], %2;\n\t"
        "selp.b32 %0, 1, 0, p;\n\t}"
        : "=r"(done) : "r"(a), "r"(parity) : "memory");
    while (!done) {
        asm volatile("{\n\t.reg .pred p;\n\t"
            "mbarrier.try_wait.parity.acquire.cluster.shared::cta.b64 p, [%1], %2, 0x989680;\n\t"
            "selp.b32 %0, 1, 0, p;\n\t}"
            : "=r"(done) : "r"(a), "r"(parity) : "memory");
    }
}
__device__ __forceinline__ void cluster_barrier() {
    asm volatile("barrier.cluster.arrive.aligned;" ::: "memory");
    asm volatile("barrier.cluster.wait.aligned;" ::: "memory");
}

__device__ __forceinline__ float sigf(float x) {
    return __fdividef(1.f, 1.f + __expf(-x));
}
__device__ __forceinline__ float tanhf_fast(float x) {
    return fmaf(2.f, sigf(2.f * x), -1.f);
}
__device__ __forceinline__ uint32_t bf16rn(float f) {
    uint32_t u = __float_as_uint(f);
    return (u + 0x7FFFu + ((u >> 16) & 1u)) >> 16;
}

// ---- f32x2 dual-FMA helpers ----
__device__ __forceinline__ u64 pkf(float lo, float hi) {
    u64 r; asm("mov.b64 %0, {%1, %2};" : "=l"(r) : "f"(lo), "f"(hi)); return r;
}
__device__ __forceinline__ u64 pku(uint32_t lo, uint32_t hi) {
    u64 r; asm("mov.b64 %0, {%1, %2};" : "=l"(r) : "r"(lo), "r"(hi)); return r;
}
__device__ __forceinline__ void upk(u64 v, float& lo, float& hi) {
    asm("mov.b64 {%0, %1}, %2;" : "=f"(lo), "=f"(hi) : "l"(v));
}
__device__ __forceinline__ void ffma2(u64& acc, u64 w, u64 h) {
    asm("fma.rn.f32x2 %0, %1, %2, %3;" : "=l"(acc) : "l"(w), "l"(h), "l"(acc));
}
// bf16x2 -> f32x2 pair; lo via shift (alu pipe)
__device__ __forceinline__ u64 wpair_shf(uint32_t w) {
    return pku(w << 16, w & 0xFFFF0000u);
}
// bf16x2 -> f32x2 pair; lo via mul (fma pipe, balances alu)
__device__ __forceinline__ u64 wpair_mul(uint32_t w) {
    uint32_t lo; asm("mul.lo.u32 %0, %1, 65536;" : "=r"(lo) : "r"(w));
    return pku(lo, w & 0xFFFF0000u);
}

// ---------------- kernel 2: clustered GRU recurrence ----------------
// cluster(2,1,1): rank r owns global j in [96r,96r+96). W_hh slice in REGISTERS
// as packed bf16 (72 u32/thread). 384 thr = (ks 0..3) x (jl 0..95).
// Exchange protocol: 2 mbarriers (local-ready / peer-ready), ONE arrive each per
// step from an elected thread after a 96-thread named barrier. Warps whose
// K-slice is own-half wait only local; peer-half warps wait the remote barrier.
__global__ void __launch_bounds__(NTHR, 1) __cluster_dims__(2, 1, 1)
gru_kernel(const int* __restrict__ char_ids,
           const float* __restrict__ w_hh_f, const float* __restrict__ b_hh_f,
           const float* __restrict__ w_hh_b, const float* __restrict__ b_hh_b) {
    __shared__ float hbuf[2][H];          // double-buffered full h
    __shared__ float part[2][9][JH];      // parity-double-buffered partials
    __shared__ int   ids_s[SEQL];
    __shared__ unsigned long long mb_loc; // armed by local elected thread
    __shared__ unsigned long long mb_rem; // armed by peer's elected thread

    const int rank = blockIdx.x;
    const int dir  = blockIdx.y;
    const int b    = blockIdx.z;
    const float* __restrict__ whh = dir ? w_hh_b : w_hh_f;
    const float* __restrict__ bhh = dir ? b_hh_b : b_hh_f;
    const float* __restrict__ proj = g_proj[dir];

    const int tid = threadIdx.x;
    const int ks  = tid / JH;            // 0..3 (uniform per warp)
    const int jl  = tid % JH;            // 0..95
    const int jg  = rank * JH + jl;      // 0..191
    const bool own_half = ((ks >> 1) == rank);  // this warp's K-slice source

    // ---- prologue ----
    if (tid == 0) { mbar_init(smem_u32(&mb_loc), 1); mbar_init(smem_u32(&mb_rem), 1); }
    ((float*)hbuf)[tid] = 0.f;
    {
        const int* __restrict__ myids = char_ids + (size_t)b * SEQL;
        for (int t = tid; t < SEQL; t += NTHR) ids_s[t] = myids[t];
    }
    // W_hh slice -> registers, packed bf16 pairs
    uint32_t wv[3][24];
#pragma unroll
    for (int g = 0; g < 3; g++) {
        const float2* __restrict__ wr2 =
            (const float2*)(whh + ((size_t)(g * H + jg)) * H + ks * KC);
#pragma unroll
        for (int q = 0; q < 24; q++) {
            float2 f = wr2[q];
            wv[g][q] = bf16rn(f.x) | (bf16rn(f.y) << 16);
        }
    }
    __syncthreads();
    cluster_barrier();   // barrier inits + hbuf visible cluster-wide

    const uint32_t loc_a = smem_u32(&mb_loc);
    const uint32_t rem_a = smem_u32(&mb_rem);
    const uint32_t peer = rank ^ 1;
    const uint32_t p_rem = mapa_u32(rem_a, peer);              // peer's mb_rem
    const uint32_t r_h0 = mapa_u32(smem_u32(&hbuf[0][jg]), peer);
    const uint32_t r_h1 = mapa_u32(smem_u32(&hbuf[1][jg]), peer);

    // arm phase 0 of both barriers (h0 = zeros already in place everywhere)
    if (tid == 0) { mbar_arrive_local(loc_a); mbar_arrive_remote(p_rem); }

    // ks0-only state
    float bhr = 0.f, bhz = 0.f, bhn = 0.f, h_j = 0.f;
    float xr = 0.f, xz = 0.f, xn = 0.f;
    float* allh_base = g_allh + ((size_t)b * SEQL) * (2 * H) + dir * H + jg;
    if (ks == 0) {
        bhr = bhh[jg]; bhz = bhh[H + jg]; bhn = bhh[2 * H + jg];
        int t0 = dir ? (SEQL - 1) : 0;
        const float* p0 = proj + (size_t)ids_s[t0] * G3 + jg;
        xr = p0[0]; xz = p0[H]; xn = p0[2 * H];
    }

#pragma unroll 1
    for (int s = 0; s < SEQL; s++) {
        const uint32_t par = (uint32_t)(s & 1);
        // wait for this step's h slice
        if (own_half) mbar_wait_parity(loc_a, par);
        else          mbar_wait_parity(rem_a, par);

        // prefetch next step's xp (ks0 only; latency hidden by the dot)
        float xrN = 0.f, xzN = 0.f, xnN = 0.f;
        if (ks == 0) {
            int sn = (s + 1 < SEQL) ? s + 1 : s;
            int tn = dir ? (SEQL - 1 - sn) : sn;
            const float* pn = proj + (size_t)ids_s[tn] * G3 + jg;
            xrN = __ldg(pn); xzN = __ldg(pn + H); xnN = __ldg(pn + 2 * H);
        }

        const float* hb = &hbuf[s & 1][ks * KC];
        u64 aR = 0, aRb = 0, aZ = 0, aZb = 0, aN = 0, aNb = 0;
#pragma unroll
        for (int q = 0; q < 12; q++) {
            float4 h4 = *(const float4*)(hb + 4 * q);
            u64 h01 = pkf(h4.x, h4.y);
            u64 h23 = pkf(h4.z, h4.w);
            if (q & 1) {  // alternate lo-extract pipe: shf (alu) vs mul (fma)
                ffma2(aR,  wpair_shf(wv[0][2 * q]),     h01);
                ffma2(aRb, wpair_shf(wv[0][2 * q + 1]), h23);
                ffma2(aZ,  wpair_shf(wv[1][2 * q]),     h01);
                ffma2(aZb, wpair_shf(wv[1][2 * q + 1]), h23);
                ffma2(aN,  wpair_shf(wv[2][2 * q]),     h01);
                ffma2(aNb, wpair_shf(wv[2][2 * q + 1]), h23);
            } else {
                ffma2(aR,  wpair_mul(wv[0][2 * q]),     h01);
                ffma2(aRb, wpair_mul(wv[0][2 * q + 1]), h23);
                ffma2(aZ,  wpair_mul(wv[1][2 * q]),     h01);
                ffma2(aZb, wpair_mul(wv[1][2 * q + 1]), h23);
                ffma2(aN,  wpair_mul(wv[2][2 * q]),     h01);
                ffma2(aNb, wpair_mul(wv[2][2 * q + 1]), h23);
            }
        }
        float r0, r1, r2, r3, z0, z1, z2, z3, n0, n1, n2, n3;
        upk(aR, r0, r1); upk(aRb, r2, r3);
        upk(aZ, z0, z1); upk(aZb, z2, z3);
        upk(aN, n0, n1); upk(aNb, n2, n3);
        float sR = (r0 + r1) + (r2 + r3);
        float sZ = (z0 + z1) + (z2 + z3);
        float sN = (n0 + n1) + (n2 + n3);

        if (ks != 0) {
            part[par][(ks - 1) * 3 + 0][jl] = sR;
            part[par][(ks - 1) * 3 + 1][jl] = sZ;
            part[par][(ks - 1) * 3 + 2][jl] = sN;
        }
        __syncthreads();   // partials visible; all local reads of hbuf[par] done

        if (ks == 0) {
            float aRt = sR + part[par][0][jl] + part[par][3][jl] + part[par][6][jl];
            float aZt = sZ + part[par][1][jl] + part[par][4][jl] + part[par][7][jl];
            float aNt = sN + part[par][2][jl] + part[par][5][jl] + part[par][8][jl];
            float r = sigf(xr + bhr + aRt);
            float z = sigf(xz + bhz + aZt);
            float n = tanhf_fast(fmaf(r, aNt + bhn, xn));
            h_j = fmaf(z, h_j - n, n);   // (1-z)*n + z*h

            hbuf[(s + 1) & 1][jg] = h_j;                 // local copy
            st_remote_f32(par ? r_h0 : r_h1, h_j);       // push to peer
            int t = dir ? (SEQL - 1 - s) : s;
            allh_base[(size_t)t * (2 * H)] = h_j;
            xr = xrN; xz = xzN; xn = xnN;

            // join the 3 ks0 warps, then single release-arrive each way
            asm volatile("bar.sync 1, 96;" ::: "memory");
            if (tid == 0) { mbar_arrive_local(loc_a); mbar_arrive_remote(p_rem); }
        }
    }

    cluster_barrier();   // no CTA exits while peer may still write into it
}

// ---------------- kernel 3: gather (unchanged, verified) ----------------
__global__ void gather_kernel(const int* __restrict__ start_ids,
                              const int* __restrict__ end_ids,
                              float* __restrict__ out) {
    const int s = blockIdx.x, b = blockIdx.y;
    const int tid = threadIdx.x;  // 192 threads, 1 float4 each
    const int st = start_ids[(size_t)b * NSPAN + s];
    const int en = end_ids[(size_t)b * NSPAN + s];
    float4* orow = (float4*)(out + ((size_t)b * NSPAN + s) * 768);
    const float4* allh = (const float4*)g_allh;
    if (tid < 96) {
        orow[tid] = allh[((size_t)b * SEQL + st) * 96 + tid];
    } else {
        orow[tid] = allh[((size_t)b * SEQL + en) * 96 + (tid - 96)];
    }
}

// ---------------- launch ----------------
extern "C" void kernel_launch(void* const* d_in, const int* in_sizes, int n_in,
                              void* d_out, int out_size) {
    const int*   char_ids  = (const int*)d_in[0];
    const int*   start_ids = (const int*)d_in[1];
    const int*   end_ids   = (const int*)d_in[2];
    const float* emb       = (const float*)d_in[3];
    const float* w_ih_f    = (const float*)d_in[4];
    const float* w_hh_f    = (const float*)d_in[5];
    const float* b_ih_f    = (const float*)d_in[6];
    const float* b_hh_f    = (const float*)d_in[7];
    const float* w_ih_b    = (const float*)d_in[8];
    const float* w_hh_b    = (const float*)d_in[9];
    const float* b_ih_b    = (const float*)d_in[10];
    const float* b_hh_b    = (const float*)d_in[11];
    float* out = (float*)d_out;

    // 1) projection tables: proj[d] = emb @ w_ih_d^T + b_ih_d  [1001, 576]
    proj_kernel<<<dim3((CHAR_VOCAB + VB - 1) / VB, 2), G3>>>(emb, w_ih_f, b_ih_f, w_ih_b, b_ih_b);

    // 2) clustered bidirectional GRU: 64 recurrences x 2-CTA clusters = 128 CTAs
    gru_kernel<<<dim3(2, 2, BATCH), NTHR>>>(char_ids, w_hh_f, b_hh_f, w_hh_b, b_hh_b);

    // 3) gather start/end hidden states into output [32, 512, 768]
    gather_kernel<<<dim3(NSPAN, BATCH), 192>>>(start_ids, end_ids, out);
}

// round 9
// speedup vs baseline: 1.6266x; 1.6266x over previous
#include <cuda_runtime.h>
#include <cstdint>

#define CHAR_VOCAB 1001
#define EMB 256
#define H 192
#define G3 576   // 3*H
#define BATCH 32
#define SEQL 2048
#define NSPAN 512

// cluster split
#define JH 96            // outputs per CTA
#define KS 4             // K-split ways
#define KC 48            // K per slice
#define NTHR (JH * KS)   // 384 threads

// ---------------- scratch (no cudaMalloc allowed) ----------------
__device__ float g_proj[2][CHAR_VOCAB * G3];                 // 2 x 2.3 MB
__device__ float g_allh[(size_t)BATCH * SEQL * 2 * H];       // 100.7 MB

// ---------------- kernel 1: proj tables (unchanged, verified) ----------------
#define VB 16
__global__ void proj_kernel(const float* __restrict__ emb,
                            const float* __restrict__ w_ih_f, const float* __restrict__ b_ih_f,
                            const float* __restrict__ w_ih_b, const float* __restrict__ b_ih_b) {
    __shared__ float embs[VB][EMB];
    const int dir = blockIdx.y;
    const float* __restrict__ w  = dir ? w_ih_b : w_ih_f;
    const float* __restrict__ bi = dir ? b_ih_b : b_ih_f;
    const int v0 = blockIdx.x * VB;

    for (int i = threadIdx.x; i < VB * EMB; i += blockDim.x) {
        int v = v0 + i / EMB;
        embs[i / EMB][i % EMB] = (v < CHAR_VOCAB) ? emb[(size_t)v * EMB + (i % EMB)] : 0.f;
    }
    __syncthreads();

    const int g = threadIdx.x;  // 0..575
    float acc[VB];
#pragma unroll
    for (int i = 0; i < VB; i++) acc[i] = 0.f;

    const float4* __restrict__ w4 = (const float4*)(w + (size_t)g * EMB);
    for (int e4 = 0; e4 < EMB / 4; e4++) {
        float4 wv = w4[e4];
#pragma unroll
        for (int i = 0; i < VB; i++) {
            float4 ev = *(const float4*)&embs[i][e4 * 4];
            acc[i] = fmaf(wv.x, ev.x, fmaf(wv.y, ev.y, fmaf(wv.z, ev.z, fmaf(wv.w, ev.w, acc[i]))));
        }
    }
    float bb = bi[g];
#pragma unroll
    for (int i = 0; i < VB; i++) {
        int v = v0 + i;
        if (v < CHAR_VOCAB) g_proj[dir][(size_t)v * G3 + g] = acc[i] + bb;
    }
}

// ---------------- PTX helpers ----------------
__device__ __forceinline__ uint32_t smem_u32(const void* p) {
    uint32_t a;
    asm("{ .reg .u64 t; cvta.to.shared.u64 t, %1; cvt.u32.u64 %0, t; }" : "=r"(a) : "l"(p));
    return a;
}
__device__ __forceinline__ uint32_t mapa_u32(uint32_t laddr, uint32_t peer) {
    uint32_t r;
    asm("mapa.shared::cluster.u32 %0, %1, %2;" : "=r"(r) : "r"(laddr), "r"(peer));
    return r;
}
__device__ __forceinline__ void mbar_init(uint32_t a, uint32_t cnt) {
    asm volatile("mbarrier.init.shared.b64 [%0], %1;" :: "r"(a), "r"(cnt) : "memory");
}
__device__ __forceinline__ void mbar_arrive_local(uint32_t a) {
    asm volatile("mbarrier.arrive.release.cluster.shared::cta.b64 _, [%0];" :: "r"(a) : "memory");
}
__device__ __forceinline__ void mbar_arrive_remote(uint32_t ra) {
    asm volatile("mbarrier.arrive.release.cluster.shared::cluster.b64 _, [%0];" :: "r"(ra) : "memory");
}
__device__ __forceinline__ void st_remote_f32(uint32_t raddr, float v) {
    asm volatile("st.shared::cluster.b32 [%0], %1;" :: "r"(raddr), "r"(__float_as_uint(v)) : "memory");
}
__device__ __forceinline__ void mbar_wait_parity(uint32_t a, uint32_t parity) {
    uint32_t done;
    asm volatile("{\n\t.reg .pred p;\n\t"
        "mbarrier.try_wait.parity.acquire.cluster.shared::cta.b64 p, [%1], %2;\n\t"
        "selp.b32 %0, 1, 0, p;\n\t}"
        : "=r"(done) : "r"(a), "r"(parity) : "memory");
    while (!done) {
        asm volatile("{\n\t.reg .pred p;\n\t"
            "mbarrier.try_wait.parity.acquire.cluster.shared::cta.b64 p, [%1], %2, 0x989680;\n\t"
            "selp.b32 %0, 1, 0, p;\n\t}"
            : "=r"(done) : "r"(a), "r"(parity) : "memory");
    }
}
__device__ __forceinline__ void cluster_barrier() {
    asm volatile("barrier.cluster.arrive.aligned;" ::: "memory");
    asm volatile("barrier.cluster.wait.aligned;" ::: "memory");
}

__device__ __forceinline__ float sigf(float x) {
    return __fdividef(1.f, 1.f + __expf(-x));
}
__device__ __forceinline__ float tanhf_fast(float x) {
    return fmaf(2.f, sigf(2.f * x), -1.f);
}
__device__ __forceinline__ uint32_t bf16rn(float f) {
    uint32_t u = __float_as_uint(f);
    return (u + 0x7FFFu + ((u >> 16) & 1u)) >> 16;
}

// one dual-MAC on a packed bf16 pair (R7 scalar form — known-good regalloc)
#define DOT2(a0, a1, w, hx, hy) { \
    float wl = __uint_as_float((w) << 16); \
    float wh = __uint_as_float((w) & 0xFFFF0000u); \
    a0 = fmaf(wl, (hx), a0); a1 = fmaf(wh, (hy), a1); }

// ---------------- kernel 2: clustered GRU recurrence ----------------
// cluster(2,1,1): rank r owns global j in [96r,96r+96). W_hh slice in REGISTERS
// as packed bf16 (72 u32/thread). 384 thr = (ks 0..3) x (jl 0..95).
// K-slice remap: kslice = (ks + 2*rank) & 3, so ks<2 always consumes the
// OWN-half of h and waits only the local barrier; ks>=2 waits the peer-armed
// barrier (DSMEM latency overlapped by the own-half dots).
// Per step each CTA issues ONE local + ONE remote release-arrive (elected
// thread after a 96-thread named barrier over the ks0 warps).
__global__ void __launch_bounds__(NTHR, 1) __cluster_dims__(2, 1, 1)
gru_kernel(const int* __restrict__ char_ids,
           const float* __restrict__ w_hh_f, const float* __restrict__ b_hh_f,
           const float* __restrict__ w_hh_b, const float* __restrict__ b_hh_b) {
    __shared__ float hbuf[2][H];          // double-buffered full h
    __shared__ float part[2][9][JH];      // parity-double-buffered partials
    __shared__ int   ids_s[SEQL];
    __shared__ unsigned long long mb_loc; // armed by local elected thread
    __shared__ unsigned long long mb_rem; // armed by peer's elected thread

    const int rank = blockIdx.x;
    const int dir  = blockIdx.y;
    const int b    = blockIdx.z;
    const float* __restrict__ whh = dir ? w_hh_b : w_hh_f;
    const float* __restrict__ bhh = dir ? b_hh_b : b_hh_f;
    const float* __restrict__ proj = g_proj[dir];

    const int tid = threadIdx.x;
    const int ks  = tid / JH;                 // 0..3 (uniform per warp)
    const int jl  = tid % JH;                 // 0..95
    const int jg  = rank * JH + jl;           // 0..191
    const int kslice = (ks + 2 * rank) & 3;   // ks<2 -> own half for BOTH ranks
    const bool own_half = (ks < 2);

    // ---- prologue ----
    if (tid == 0) { mbar_init(smem_u32(&mb_loc), 1); mbar_init(smem_u32(&mb_rem), 1); }
    ((float*)hbuf)[tid] = 0.f;
    {
        const int* __restrict__ myids = char_ids + (size_t)b * SEQL;
        for (int t = tid; t < SEQL; t += NTHR) ids_s[t] = myids[t];
    }
    // W_hh slice -> registers, packed bf16 pairs: wv[g][q] = (k=2q lo, k=2q+1 hi)
    uint32_t wv[3][24];
#pragma unroll
    for (int g = 0; g < 3; g++) {
        const float2* __restrict__ wr2 =
            (const float2*)(whh + ((size_t)(g * H + jg)) * H + kslice * KC);
#pragma unroll
        for (int q = 0; q < 24; q++) {
            float2 f = wr2[q];
            wv[g][q] = bf16rn(f.x) | (bf16rn(f.y) << 16);
        }
    }
    __syncthreads();
    cluster_barrier();   // barrier inits + zeroed hbuf visible cluster-wide

    const uint32_t loc_a = smem_u32(&mb_loc);
    const uint32_t rem_a = smem_u32(&mb_rem);
    const uint32_t peer = rank ^ 1;
    const uint32_t p_rem = mapa_u32(rem_a, peer);              // peer's mb_rem
    const uint32_t r_h0 = mapa_u32(smem_u32(&hbuf[0][jg]), peer);
    const uint32_t r_h1 = mapa_u32(smem_u32(&hbuf[1][jg]), peer);

    // arm phase 0 of both barriers (h for step 0 = zeros, already in place)
    if (tid == 0) { mbar_arrive_local(loc_a); mbar_arrive_remote(p_rem); }

    // ks0-only state
    float bhr = 0.f, bhz = 0.f, bhn = 0.f, h_j = 0.f;
    float xr = 0.f, xz = 0.f, xn = 0.f;
    float* allh_base = g_allh + ((size_t)b * SEQL) * (2 * H) + dir * H + jg;
    if (ks == 0) {
        bhr = bhh[jg]; bhz = bhh[H + jg]; bhn = bhh[2 * H + jg];
        int t0 = dir ? (SEQL - 1) : 0;
        const float* p0 = proj + (size_t)ids_s[t0] * G3 + jg;
        xr = p0[0]; xz = p0[H]; xn = p0[2 * H];
    }

#pragma unroll 1
    for (int s = 0; s < SEQL; s++) {
        const uint32_t par = (uint32_t)(s & 1);
        // wait for this step's h slice (own half: local elect; peer half: remote elect)
        if (own_half) mbar_wait_parity(loc_a, par);
        else          mbar_wait_parity(rem_a, par);

        // prefetch next step's xp (ks0 only; latency hidden by the dot)
        float xrN = 0.f, xzN = 0.f, xnN = 0.f;
        if (ks == 0) {
            int sn = (s + 1 < SEQL) ? s + 1 : s;
            int tn = dir ? (SEQL - 1 - sn) : sn;
            const float* pn = proj + (size_t)ids_s[tn] * G3 + jg;
            xrN = __ldg(pn); xzN = __ldg(pn + H); xnN = __ldg(pn + 2 * H);
        }

        const float* hb = &hbuf[par][kslice * KC];
        float aR0 = 0.f, aR1 = 0.f, aZ0 = 0.f, aZ1 = 0.f, aN0 = 0.f, aN1 = 0.f;
#pragma unroll
        for (int q = 0; q < 12; q++) {
            float4 h4 = *(const float4*)(hb + 4 * q);
            DOT2(aR0, aR1, wv[0][2 * q],     h4.x, h4.y);
            DOT2(aR0, aR1, wv[0][2 * q + 1], h4.z, h4.w);
            DOT2(aZ0, aZ1, wv[1][2 * q],     h4.x, h4.y);
            DOT2(aZ0, aZ1, wv[1][2 * q + 1], h4.z, h4.w);
            DOT2(aN0, aN1, wv[2][2 * q],     h4.x, h4.y);
            DOT2(aN0, aN1, wv[2][2 * q + 1], h4.z, h4.w);
        }

        if (ks != 0) {
            part[par][(ks - 1) * 3 + 0][jl] = aR0 + aR1;
            part[par][(ks - 1) * 3 + 1][jl] = aZ0 + aZ1;
            part[par][(ks - 1) * 3 + 2][jl] = aN0 + aN1;
        }
        __syncthreads();   // partials visible; all local reads of hbuf[par] done

        if (ks == 0) {
            float aRt = aR0 + aR1 + part[par][0][jl] + part[par][3][jl] + part[par][6][jl];
            float aZt = aZ0 + aZ1 + part[par][1][jl] + part[par][4][jl] + part[par][7][jl];
            float aNt = aN0 + aN1 + part[par][2][jl] + part[par][5][jl] + part[par][8][jl];
            float r = sigf(xr + bhr + aRt);
            float z = sigf(xz + bhz + aZt);
            float n = tanhf_fast(fmaf(r, aNt + bhn, xn));
            h_j = fmaf(z, h_j - n, n);   // (1-z)*n + z*h

            hbuf[(s + 1) & 1][jg] = h_j;                 // local copy
            st_remote_f32(par ? r_h0 : r_h1, h_j);       // push to peer's copy
            int t = dir ? (SEQL - 1 - s) : s;
            allh_base[(size_t)t * (2 * H)] = h_j;
            xr = xrN; xz = xzN; xn = xnN;

            // join the 3 ks0 warps, then ONE release-arrive each way
            asm volatile("bar.sync 1, 96;" ::: "memory");
            if (tid == 0) { mbar_arrive_local(loc_a); mbar_arrive_remote(p_rem); }
        }
    }

    cluster_barrier();   // no CTA exits while peer may still write into it
}

// ---------------- kernel 3: gather (unchanged, verified) ----------------
__global__ void gather_kernel(const int* __restrict__ start_ids,
                              const int* __restrict__ end_ids,
                              float* __restrict__ out) {
    const int s = blockIdx.x, b = blockIdx.y;
    const int tid = threadIdx.x;  // 192 threads, 1 float4 each
    const int st = start_ids[(size_t)b * NSPAN + s];
    const int en = end_ids[(size_t)b * NSPAN + s];
    float4* orow = (float4*)(out + ((size_t)b * NSPAN + s) * 768);
    const float4* allh = (const float4*)g_allh;
    if (tid < 96) {
        orow[tid] = allh[((size_t)b * SEQL + st) * 96 + tid];
    } else {
        orow[tid] = allh[((size_t)b * SEQL + en) * 96 + (tid - 96)];
    }
}

// ---------------- launch ----------------
extern "C" void kernel_launch(void* const* d_in, const int* in_sizes, int n_in,
                              void* d_out, int out_size) {
    const int*   char_ids  = (const int*)d_in[0];
    const int*   start_ids = (const int*)d_in[1];
    const int*   end_ids   = (const int*)d_in[2];
    const float* emb       = (const float*)d_in[3];
    const float* w_ih_f    = (const float*)d_in[4];
    const float* w_hh_f    = (const float*)d_in[5];
    const float* b_ih_f    = (const float*)d_in[6];
    const float* b_hh_f    = (const float*)d_in[7];
    const float* w_ih_b    = (const float*)d_in[8];
    const float* w_hh_b    = (const float*)d_in[9];
    const float* b_ih_b    = (const float*)d_in[10];
    const float* b_hh_b    = (const float*)d_in[11];
    float* out = (float*)d_out;

    // 1) projection tables: proj[d] = emb @ w_ih_d^T + b_ih_d  [1001, 576]
    proj_kernel<<<dim3((CHAR_VOCAB + VB - 1) / VB, 2), G3>>>(emb, w_ih_f, b_ih_f, w_ih_b, b_ih_b);

    // 2) clustered bidirectional GRU: 64 recurrences x 2-CTA clusters = 128 CTAs
    gru_kernel<<<dim3(2, 2, BATCH), NTHR>>>(char_ids, w_hh_f, b_hh_f, w_hh_b, b_hh_b);

    // 3) gather start/end hidden states into output [32, 512, 768]
    gather_kernel<<<dim3(NSPAN, BATCH), 192>>>(start_ids, end_ids, out);
}